// round 1
// baseline (speedup 1.0000x reference)
#include <cuda_runtime.h>
#include <math.h>

// Problem dims (fixed by the dataset)
#define NT 2048      // tokens (B*S)
#define NE 8         // experts
#define ND 1024      // d_model
#define NF 2048      // d_ff
#define TOPK 2

// -------- scratch (alloc-free: __device__ globals) --------
__device__ int   g_cnt[NE];                       // tokens routed to each expert
__device__ int   g_tok[NE * NT];                  // token id per (expert, slot)
__device__ float g_wgt[NE * NT];                  // combine weight per (expert, slot)
__device__ float g_h[(size_t)NE * NT * NF];       // silu(x@W1) activations, 134 MB

// ---------------------------------------------------------------------------
// Kernel 0: zero output + expert counters
// ---------------------------------------------------------------------------
__global__ void k_zero(float* __restrict__ out) {
    int i = blockIdx.x * blockDim.x + threadIdx.x;
    if (i < NT * ND) out[i] = 0.0f;
    if (i < NE) g_cnt[i] = 0;
}

// ---------------------------------------------------------------------------
// Kernel 1: router — softmax over 8 logits, top-2, renormalize, dispatch
// ---------------------------------------------------------------------------
__global__ void k_router(const float* __restrict__ logits) {
    int t = blockIdx.x * blockDim.x + threadIdx.x;
    if (t >= NT) return;
    float l[NE];
#pragma unroll
    for (int e = 0; e < NE; e++) l[e] = logits[t * NE + e];

    // argmax
    int i0 = 0;
#pragma unroll
    for (int e = 1; e < NE; e++) if (l[e] > l[i0]) i0 = e;
    // second argmax
    int i1 = -1; float best = -1e30f;
#pragma unroll
    for (int e = 0; e < NE; e++) {
        if (e != i0 && l[e] > best) { best = l[e]; i1 = e; }
    }
    // renormalized top-2 softmax weights: w0 = p0/(p0+p1) = sigmoid(l0-l1)
    float w0 = 1.0f / (1.0f + expf(l[i1] - l[i0]));
    float w1 = 1.0f - w0;

    int s0 = atomicAdd(&g_cnt[i0], 1);
    g_tok[i0 * NT + s0] = t;
    g_wgt[i0 * NT + s0] = w0;
    int s1 = atomicAdd(&g_cnt[i1], 1);
    g_tok[i1 * NT + s1] = t;
    g_wgt[i1 * NT + s1] = w1;
}

// ---------------------------------------------------------------------------
// Kernel 2: grouped GEMM1 + SiLU
//   H[e, m, n] = silu( sum_k x[tok[e,m], k] * W1[e, k, n] )
//   tiles: BM=64, BN=64, BK=16; 256 threads; 4x4 register micro-tile
// ---------------------------------------------------------------------------
__global__ void k_gemm1(const float* __restrict__ x, const float* __restrict__ W1) {
    const int e   = blockIdx.z;
    const int cnt = g_cnt[e];
    const int m0  = blockIdx.x * 64;
    if (m0 >= cnt) return;
    const int n0  = blockIdx.y * 64;

    __shared__ float As[16][68];   // [k][m], padded
    __shared__ float Bs[16][64];   // [k][n]

    const int tid = threadIdx.x;
    const int ty  = tid >> 4;      // 0..15 -> m group
    const int tx  = tid & 15;      // 0..15 -> n group

    const int*   tok = &g_tok[e * NT];
    const float* W   = W1 + (size_t)e * ND * NF;

    float acc[4][4];
#pragma unroll
    for (int i = 0; i < 4; i++)
#pragma unroll
        for (int j = 0; j < 4; j++) acc[i][j] = 0.0f;

    for (int k0 = 0; k0 < ND; k0 += 16) {
        // load A tile (gathered rows), transposed into As[k][m]
#pragma unroll
        for (int it = 0; it < 4; it++) {
            int i = tid + it * 256;           // 0..1023
            int r = i >> 4, c = i & 15;
            float v = 0.0f;
            int row = m0 + r;
            if (row < cnt) v = x[(size_t)tok[row] * ND + k0 + c];
            As[c][r] = v;
        }
        // load B tile
#pragma unroll
        for (int it = 0; it < 4; it++) {
            int i = tid + it * 256;           // 0..1023
            int r = i >> 6, c = i & 63;
            Bs[r][c] = W[(size_t)(k0 + r) * NF + n0 + c];
        }
        __syncthreads();

#pragma unroll
        for (int k = 0; k < 16; k++) {
            float a[4], b[4];
#pragma unroll
            for (int j = 0; j < 4; j++) a[j] = As[k][ty * 4 + j];
#pragma unroll
            for (int j = 0; j < 4; j++) b[j] = Bs[k][tx * 4 + j];
#pragma unroll
            for (int i = 0; i < 4; i++)
#pragma unroll
                for (int j = 0; j < 4; j++) acc[i][j] = fmaf(a[i], b[j], acc[i][j]);
        }
        __syncthreads();
    }

    float* H = &g_h[(size_t)(e * NT) * NF];
#pragma unroll
    for (int i = 0; i < 4; i++) {
        int row = m0 + ty * 4 + i;
        if (row < cnt) {
#pragma unroll
            for (int j = 0; j < 4; j++) {
                float v = acc[i][j];
                float s = v / (1.0f + expf(-v));   // silu
                H[(size_t)row * NF + n0 + tx * 4 + j] = s;
            }
        }
    }
}

// ---------------------------------------------------------------------------
// Kernel 3: grouped GEMM2 + weighted scatter-combine
//   out[tok[e,m], n] += wgt[e,m] * sum_k H[e, m, k] * W2[e, k, n]
// ---------------------------------------------------------------------------
__global__ void k_gemm2(const float* __restrict__ W2, float* __restrict__ out) {
    const int e   = blockIdx.z;
    const int cnt = g_cnt[e];
    const int m0  = blockIdx.x * 64;
    if (m0 >= cnt) return;
    const int n0  = blockIdx.y * 64;

    __shared__ float As[16][68];
    __shared__ float Bs[16][64];

    const int tid = threadIdx.x;
    const int ty  = tid >> 4;
    const int tx  = tid & 15;

    const float* H = &g_h[(size_t)(e * NT) * NF];
    const float* W = W2 + (size_t)e * NF * ND;

    float acc[4][4];
#pragma unroll
    for (int i = 0; i < 4; i++)
#pragma unroll
        for (int j = 0; j < 4; j++) acc[i][j] = 0.0f;

    for (int k0 = 0; k0 < NF; k0 += 16) {
#pragma unroll
        for (int it = 0; it < 4; it++) {
            int i = tid + it * 256;
            int r = i >> 4, c = i & 15;
            float v = 0.0f;
            int row = m0 + r;
            if (row < cnt) v = H[(size_t)row * NF + k0 + c];
            As[c][r] = v;
        }
#pragma unroll
        for (int it = 0; it < 4; it++) {
            int i = tid + it * 256;
            int r = i >> 6, c = i & 63;
            Bs[r][c] = W[(size_t)(k0 + r) * ND + n0 + c];
        }
        __syncthreads();

#pragma unroll
        for (int k = 0; k < 16; k++) {
            float a[4], b[4];
#pragma unroll
            for (int j = 0; j < 4; j++) a[j] = As[k][ty * 4 + j];
#pragma unroll
            for (int j = 0; j < 4; j++) b[j] = Bs[k][tx * 4 + j];
#pragma unroll
            for (int i = 0; i < 4; i++)
#pragma unroll
                for (int j = 0; j < 4; j++) acc[i][j] = fmaf(a[i], b[j], acc[i][j]);
        }
        __syncthreads();
    }

#pragma unroll
    for (int i = 0; i < 4; i++) {
        int row = m0 + ty * 4 + i;
        if (row < cnt) {
            float w = g_wgt[e * NT + row];
            int   t = g_tok[e * NT + row];
#pragma unroll
            for (int j = 0; j < 4; j++) {
                atomicAdd(&out[(size_t)t * ND + n0 + tx * 4 + j], w * acc[i][j]);
            }
        }
    }
}

// ---------------------------------------------------------------------------
// launch
// ---------------------------------------------------------------------------
extern "C" void kernel_launch(void* const* d_in, const int* in_sizes, int n_in,
                              void* d_out, int out_size) {
    const float* hidden = (const float*)d_in[0];   // [B,S,D] = [T, D]
    const float* logits = (const float*)d_in[1];   // [T, E]
    const float* W1     = (const float*)d_in[2];   // [E, D, F]
    const float* W2     = (const float*)d_in[3];   // [E, F, D]
    float* out = (float*)d_out;                    // [T, D]

    k_zero<<<(NT * ND + 255) / 256, 256>>>(out);
    k_router<<<(NT + 255) / 256, 256>>>(logits);

    dim3 g1(NT / 64, NF / 64, NE);   // (32, 32, 8); blocks past cnt[e] exit early
    k_gemm1<<<g1, 256>>>(hidden, W1);

    dim3 g2(NT / 64, ND / 64, NE);   // (32, 16, 8)
    k_gemm2<<<g2, 256>>>(W2, out);
}